// round 1
// baseline (speedup 1.0000x reference)
#include <cuda_runtime.h>
#include <cuda_bf16.h>
#include <cstdint>

#define NN 10000
#define EE 40000
#define GG 128
#define NF 92
#define EF 50
#define HH 64
#define NHD 10
#define GD 108
#define LL 5
#define FPH 640   // NH*H

// ---------------- device scratch (static, no runtime alloc) ----------------
__device__ float g_h[NN * HH];
__device__ float g_init[NN * HH];
__device__ float g_ea[EE * HH];
__device__ float g_Hn[NN * FPH];     // h @ W[:64]   (25.6 MB)
__device__ float g_P[EE * FPH];      // ea @ W[64:]  (102.4 MB)
__device__ float g_agg[NN * HH];
__device__ float g_score[NN];
__device__ float g_smax[GG];
__device__ float g_den[GG];
__device__ float g_pool[GG * HH];

__device__ __forceinline__ float lrelu(float v) { return v > 0.f ? v : 0.2f * v; }

__device__ __forceinline__ float warp_sum(float v) {
    v += __shfl_down_sync(0xffffffffu, v, 16);
    v += __shfl_down_sync(0xffffffffu, v, 8);
    v += __shfl_down_sync(0xffffffffu, v, 4);
    v += __shfl_down_sync(0xffffffffu, v, 2);
    v += __shfl_down_sync(0xffffffffu, v, 1);
    return v;
}

__device__ __forceinline__ void atomicMaxFloat(float* addr, float val) {
    int* ai = (int*)addr;
    int old = *ai;
    while (__int_as_float(old) < val) {
        int assumed = old;
        old = atomicCAS(ai, assumed, __float_as_int(val));
        if (old == assumed) break;
    }
}

// ---------------- embeddings ----------------
// one block (64 threads) per node: h = lrelu(x @ node_W + b), also save initial
__global__ void embed_node_kernel(const float* __restrict__ x,
                                  const float* __restrict__ W,
                                  const float* __restrict__ b) {
    int n = blockIdx.x;
    int t = threadIdx.x;
    __shared__ float xs[NF];
    for (int k = t; k < NF; k += 64) xs[k] = x[n * NF + k];
    __syncthreads();
    float acc = b[t];
    #pragma unroll 4
    for (int k = 0; k < NF; k++) acc = fmaf(xs[k], W[k * HH + t], acc);
    float v = lrelu(acc);
    g_h[n * HH + t] = v;
    g_init[n * HH + t] = v;
}

__global__ void embed_edge_kernel(const float* __restrict__ ea,
                                  const float* __restrict__ W,
                                  const float* __restrict__ b) {
    int e = blockIdx.x;
    int t = threadIdx.x;
    __shared__ float xs[EF];
    if (t < EF) xs[t] = ea[e * EF + t];
    __syncthreads();
    float acc = b[t];
    #pragma unroll 5
    for (int k = 0; k < EF; k++) acc = fmaf(xs[k], W[k * HH + t], acc);
    g_ea[e * HH + t] = lrelu(acc);
}

// ---------------- init scratch ----------------
__global__ void init_misc_kernel() {
    int idx = blockIdx.x * 256 + threadIdx.x;
    if (idx < NN * HH) g_agg[idx] = 0.f;
    if (idx < GG * HH) g_pool[idx] = 0.f;
    if (idx < GG) { g_smax[idx] = -3.0e38f; g_den[idx] = 0.f; }
}

// ---------------- GEMM: C[M,640] = A[M,64] @ W[64,640] ----------------
// 64x64 tile, K=64 full, 256 threads, 4x4 micro-tile per thread.
__device__ __forceinline__ void gemm_body(const float* __restrict__ A,
                                          const float* __restrict__ W,
                                          float* __restrict__ C, int M) {
    __shared__ float As[64][65];
    __shared__ float Bs[64][65];
    int bm = blockIdx.x * 64;
    int bn = blockIdx.y * 64;
    int tid = threadIdx.x;
    #pragma unroll
    for (int i = 0; i < 16; i++) {
        int lin = tid + i * 256;
        int r = lin >> 6, c = lin & 63;
        int m = bm + r;
        As[r][c] = (m < M) ? A[m * 64 + c] : 0.f;
        Bs[r][c] = W[r * FPH + bn + c];
    }
    __syncthreads();
    int tx = tid & 15, ty = tid >> 4;
    float acc[4][4] = {};
    #pragma unroll
    for (int k = 0; k < 64; k++) {
        float a[4], bv[4];
        #pragma unroll
        for (int i = 0; i < 4; i++) a[i] = As[ty * 4 + i][k];
        #pragma unroll
        for (int j = 0; j < 4; j++) bv[j] = Bs[k][tx * 4 + j];
        #pragma unroll
        for (int i = 0; i < 4; i++)
            #pragma unroll
            for (int j = 0; j < 4; j++) acc[i][j] = fmaf(a[i], bv[j], acc[i][j]);
    }
    #pragma unroll
    for (int i = 0; i < 4; i++) {
        int m = bm + ty * 4 + i;
        if (m < M) {
            #pragma unroll
            for (int j = 0; j < 4; j++)
                C[(size_t)m * FPH + bn + tx * 4 + j] = acc[i][j];
        }
    }
}

__global__ void gemm_Hn_kernel(const float* __restrict__ W) { gemm_body(g_h, W, g_Hn, NN); }
__global__ void gemm_P_kernel(const float* __restrict__ W) { gemm_body(g_ea, W, g_P, EE); }

// ---------------- fused edge kernel ----------------
// 4 edges per 256-thread block; 64 threads per edge (thread t = channel t of each head)
__global__ void edge_kernel(const float* __restrict__ att,
                            const float* __restrict__ gamma,
                            const float* __restrict__ beta,
                            const int* __restrict__ ei) {
    __shared__ float red[4][2][NHD];
    __shared__ float salpha[4][NHD];
    const float inv_std = 0.99999500003749969f; // 1/sqrt(1+1e-5)

    int tid = threadIdx.x;
    int grp = tid >> 6;
    int t = tid & 63;
    int e = blockIdx.x * 4 + grp;

    int row = ei[e];
    int col = ei[EE + e];

    const float* Pp = g_P + (size_t)e * FPH;
    const float* Hr = g_Hn + (size_t)row * FPH;
    const float* Hc = g_Hn + (size_t)col * FPH;

    float hj[NHD];
    float ap[NHD];
    #pragma unroll
    for (int nh = 0; nh < NHD; nh++) {
        int idx = nh * 64 + t;
        float p = Pp[idx];
        float vi = lrelu(Hr[idx] + p);
        float vj = lrelu(Hc[idx] + p);
        hj[nh] = vj;
        ap[nh] = fmaf(vi, att[nh * 128 + t], vj * att[nh * 128 + 64 + t]);
    }
    int warp_in_grp = t >> 5;
    #pragma unroll
    for (int nh = 0; nh < NHD; nh++) {
        float v = warp_sum(ap[nh]);
        if ((t & 31) == 0) red[grp][warp_in_grp][nh] = v;
    }
    __syncthreads();
    if (t == 0) {
        float a[NHD];
        float mx = -3.0e38f;
        #pragma unroll
        for (int nh = 0; nh < NHD; nh++) {
            float v = red[grp][0][nh] + red[grp][1][nh];
            v = lrelu(v);
            v = fmaf(v * inv_std, gamma[nh], beta[nh]);
            a[nh] = v;
            mx = fmaxf(mx, v);
        }
        float s = 0.f;
        #pragma unroll
        for (int nh = 0; nh < NHD; nh++) { a[nh] = __expf(a[nh] - mx); s += a[nh]; }
        float inv = 0.1f / s;  // fold mean-over-heads into alpha
        #pragma unroll
        for (int nh = 0; nh < NHD; nh++) salpha[grp][nh] = a[nh] * inv;
    }
    __syncthreads();
    float m = 0.f;
    #pragma unroll
    for (int nh = 0; nh < NHD; nh++) m = fmaf(salpha[grp][nh], hj[nh], m);
    atomicAdd(&g_agg[row * HH + t], m);
}

// ---------------- node update: h = (i>0? h:0) + agg + b [+ initial on last] ----
__global__ void node_update_kernel(const float* __restrict__ b, int flags) {
    int idx = blockIdx.x * 256 + threadIdx.x;
    if (idx >= NN * HH) return;
    int t = idx & 63;
    float v = g_agg[idx] + b[t];
    if (flags & 1) v += g_h[idx];
    if (flags & 2) v += g_init[idx];
    g_h[idx] = v;
    g_agg[idx] = 0.f;
}

// ---------------- readout ----------------
// score[n] = (lrelu([h[n],g] @ ga_W1 + b1) @ ga_W2 + b2)
__global__ void score_kernel(const int* __restrict__ batch,
                             const float* __restrict__ gfeat,
                             const float* __restrict__ W1,
                             const float* __restrict__ b1,
                             const float* __restrict__ W2,
                             const float* __restrict__ b2) {
    int n = blockIdx.x;
    int t = threadIdx.x;
    __shared__ float cat_s[HH + GD];
    __shared__ float wr[2];
    int bidx = batch[n];
    cat_s[t] = g_h[n * HH + t];
    for (int k = t; k < GD; k += 64) cat_s[HH + k] = gfeat[bidx * GD + k];
    __syncthreads();
    float acc = b1[t];
    #pragma unroll 4
    for (int k = 0; k < HH + GD; k++) acc = fmaf(cat_s[k], W1[k * HH + t], acc);
    float s = lrelu(acc);
    float v = warp_sum(s * W2[t]);
    if ((t & 31) == 0) wr[t >> 5] = v;
    __syncthreads();
    if (t == 0) g_score[n] = wr[0] + wr[1] + b2[0];
}

__global__ void smax_kernel(const int* __restrict__ batch) {
    int n = blockIdx.x * 256 + threadIdx.x;
    if (n >= NN) return;
    atomicMaxFloat(&g_smax[batch[n]], g_score[n]);
}

__global__ void expden_kernel(const int* __restrict__ batch) {
    int n = blockIdx.x * 256 + threadIdx.x;
    if (n >= NN) return;
    int b = batch[n];
    float ex = __expf(g_score[n] - g_smax[b]);
    g_score[n] = ex;
    atomicAdd(&g_den[b], ex);
}

__global__ void pool_kernel(const int* __restrict__ batch) {
    int n = blockIdx.x;
    int t = threadIdx.x;
    int b = batch[n];
    float w = g_score[n] / g_den[b];
    atomicAdd(&g_pool[b * HH + t], g_h[n * HH + t] * w);
}

__global__ void out_kernel(const float* __restrict__ W1,
                           const float* __restrict__ b1,
                           const float* __restrict__ W2,
                           const float* __restrict__ b2,
                           float* __restrict__ out) {
    int g = blockIdx.x;
    int t = threadIdx.x;
    __shared__ float ps[HH];
    __shared__ float wr[2];
    ps[t] = g_pool[g * HH + t];
    __syncthreads();
    float acc = b1[t];
    #pragma unroll 4
    for (int k = 0; k < HH; k++) acc = fmaf(ps[k], W1[k * HH + t], acc);
    float r = fmaxf(acc, 0.f);
    float v = warp_sum(r * W2[t]);
    if ((t & 31) == 0) wr[t >> 5] = v;
    __syncthreads();
    if (t == 0) out[g] = wr[0] + wr[1] + b2[0];
}

// ---------------- launch ----------------
extern "C" void kernel_launch(void* const* d_in, const int* in_sizes, int n_in,
                              void* d_out, int out_size) {
    const float* x        = (const float*)d_in[0];
    const int*   ei       = (const int*)  d_in[1];
    const float* eattr    = (const float*)d_in[2];
    const int*   batch    = (const int*)  d_in[3];
    const float* gfeat    = (const float*)d_in[4];
    const float* node_W   = (const float*)d_in[5];
    const float* node_b   = (const float*)d_in[6];
    const float* edge_W   = (const float*)d_in[7];
    const float* edge_b   = (const float*)d_in[8];
    const float* conv_W   = (const float*)d_in[9];
    const float* conv_att = (const float*)d_in[10];
    const float* conv_b   = (const float*)d_in[11];
    const float* conv_g   = (const float*)d_in[12];
    const float* conv_be  = (const float*)d_in[13];
    const float* ga_W1    = (const float*)d_in[14];
    const float* ga_b1    = (const float*)d_in[15];
    const float* ga_W2    = (const float*)d_in[16];
    const float* ga_b2    = (const float*)d_in[17];
    const float* out_W1   = (const float*)d_in[18];
    const float* out_b1   = (const float*)d_in[19];
    const float* out_W2   = (const float*)d_in[20];
    const float* out_b2   = (const float*)d_in[21];
    float* out = (float*)d_out;

    embed_node_kernel<<<NN, 64>>>(x, node_W, node_b);
    embed_edge_kernel<<<EE, 64>>>(eattr, edge_W, edge_b);
    init_misc_kernel<<<(NN * HH + 255) / 256, 256>>>();

    for (int i = 0; i < LL; i++) {
        const float* Wi = conv_W + (size_t)i * 2 * HH * FPH;
        gemm_Hn_kernel<<<dim3((NN + 63) / 64, FPH / 64), 256>>>(Wi);
        gemm_P_kernel<<<dim3(EE / 64, FPH / 64), 256>>>(Wi + (size_t)HH * FPH);
        edge_kernel<<<EE / 4, 256>>>(conv_att + (size_t)i * NHD * 2 * HH,
                                     conv_g + i * NHD, conv_be + i * NHD, ei);
        int flags = (i > 0 ? 1 : 0) | (i == LL - 1 ? 2 : 0);
        node_update_kernel<<<(NN * HH + 255) / 256, 256>>>(conv_b + i * HH, flags);
    }

    score_kernel<<<NN, 64>>>(batch, gfeat, ga_W1, ga_b1, ga_W2, ga_b2);
    smax_kernel<<<(NN + 255) / 256, 256>>>(batch);
    expden_kernel<<<(NN + 255) / 256, 256>>>(batch);
    pool_kernel<<<NN, 64>>>(batch);
    out_kernel<<<GG, 64>>>(out_W1, out_b1, out_W2, out_b2, out);
}